// round 1
// baseline (speedup 1.0000x reference)
#include <cuda_runtime.h>
#include <cuda_bf16.h>
#include <cstdint>

#define FULL 0xffffffffu

// One warp per token. E = 256 experts, 8 groups of 32.
// Lane l owns experts [l*8, l*8+8)  -> all in group (l>>2); groups are 4-lane segments.
__global__ void __launch_bounds__(256)
noaux_router_kernel(const float* __restrict__ logits,
                    const float* __restrict__ bias,
                    float* __restrict__ out,
                    int T, int write_ids)
{
    const int warp = blockIdx.x * (blockDim.x >> 5) + (threadIdx.x >> 5);
    if (warp >= T) return;
    const int lane = threadIdx.x & 31;

    // ---- load 8 logits + 8 biases (2x LDG.128 each) ----
    const float4* lp = reinterpret_cast<const float4*>(logits + (size_t)warp * 256);
    float4 x0 = lp[lane * 2];
    float4 x1 = lp[lane * 2 + 1];
    const float4* bp = reinterpret_cast<const float4*>(bias);
    float4 b0 = bp[lane * 2];
    float4 b1 = bp[lane * 2 + 1];

    float xv[8] = {x0.x, x0.y, x0.z, x0.w, x1.x, x1.y, x1.z, x1.w};
    float bv[8] = {b0.x, b0.y, b0.z, b0.w, b1.x, b1.y, b1.z, b1.w};

    float sig[8];   // uncorrected sigmoid (weights)
    float mk[8];    // corrected score, later masked
    #pragma unroll
    for (int i = 0; i < 8; i++) {
        float e = __expf(-xv[i]);
        sig[i] = 1.0f / (1.0f + e);      // rcp + newton: ~1e-7 accurate
        mk[i]  = sig[i] + bv[i];         // corrected score (selection only)
    }

    // ---- group score = sum of top-2 corrected within group ----
    float m1 = -INFINITY, m2 = -INFINITY;
    #pragma unroll
    for (int i = 0; i < 8; i++) {
        float v   = mk[i];
        float nm2 = fmaxf(m2, fminf(m1, v));
        m1 = fmaxf(m1, v);
        m2 = nm2;
    }
    #pragma unroll
    for (int d = 1; d < 4; d <<= 1) {    // reduce within 4-lane group segment
        float o1 = __shfl_xor_sync(FULL, m1, d);
        float o2 = __shfl_xor_sync(FULL, m2, d);
        float nm2 = fmaxf(fminf(m1, o1), fmaxf(m2, o2));
        m1 = fmaxf(m1, o1);
        m2 = nm2;
    }
    const float gscore = m1 + m2;        // identical across each 4-lane segment
    const int   myg    = lane >> 2;

    // ---- top-4 groups (tie-break: lowest group index) ----
    float gs[8];
    #pragma unroll
    for (int g = 0; g < 8; g++) gs[g] = __shfl_sync(FULL, gscore, g * 4);
    int cnt = 0;
    const float s_my = gs[myg];
    #pragma unroll
    for (int g = 0; g < 8; g++)
        cnt += (gs[g] > s_my) || (gs[g] == s_my && g < myg);
    const bool sel = (cnt < 4);

    // ---- mask: non-selected groups get exactly 0.0 (matches reference) ----
    #pragma unroll
    for (int i = 0; i < 8; i++)
        mk[i] = sel ? mk[i] : 0.0f;

    // ---- local argmax state (mval, midx, mw) ----
    float mval = mk[0]; int midx = 0; float mw = sig[0];
    #pragma unroll
    for (int i = 1; i < 8; i++) {
        if (mk[i] > mval) { mval = mk[i]; midx = i; mw = sig[i]; }
    }

    // ---- global top-8: 8 rounds of warp argmax (tie-break: lowest index) ----
    float wsum = 0.0f;
    float myw  = 0.0f;
    int   myid = 0;
    #pragma unroll
    for (int it = 0; it < 8; it++) {
        float v  = mval;
        int   gi = (lane << 3) | midx;
        #pragma unroll
        for (int d = 16; d > 0; d >>= 1) {
            float ov  = __shfl_xor_sync(FULL, v,  d);
            int   ogi = __shfl_xor_sync(FULL, gi, d);
            if (ov > v || (ov == v && ogi < gi)) { v = ov; gi = ogi; }
        }
        const int wlane = gi >> 3;
        const float w = __shfl_sync(FULL, mw, wlane);  // winner lane's mw == sig[winning slot]
        wsum += w;
        if (lane == it) { myw = w; myid = gi; }

        // remove winner from its owner's list (branchless, no dynamic indexing)
        #pragma unroll
        for (int i = 0; i < 8; i++)
            if (lane == wlane && i == midx) mk[i] = -INFINITY;
        // rescan (all lanes; only winner's state actually changes)
        mval = mk[0]; midx = 0; mw = sig[0];
        #pragma unroll
        for (int i = 1; i < 8; i++) {
            if (mk[i] > mval) { mval = mk[i]; midx = i; mw = sig[i]; }
        }
    }

    // ---- write: weights [T*8], then ids [T*8] (as float) ----
    if (lane < 8) {
        const float scale = 2.5f / (wsum + 1e-20f);
        out[(size_t)warp * 8 + lane] = myw * scale;
        if (write_ids)
            out[(size_t)T * 8 + (size_t)warp * 8 + lane] = (float)myid;
    }
}

extern "C" void kernel_launch(void* const* d_in, const int* in_sizes, int n_in,
                              void* d_out, int out_size)
{
    const float* logits = (const float*)d_in[0];
    const float* bias   = (const float*)d_in[1];
    const int E = in_sizes[1];            // 256
    const int T = in_sizes[0] / E;        // 131072
    float* out = (float*)d_out;

    const int write_ids = (out_size >= T * 16) ? 1 : 0;

    const int warps_per_block = 8;        // 256 threads
    const int blocks = (T + warps_per_block - 1) / warps_per_block;
    noaux_router_kernel<<<blocks, 256>>>(logits, bias, out, T, write_ids);
}

// round 2
// speedup vs baseline: 1.6922x; 1.6922x over previous
#include <cuda_runtime.h>
#include <cuda_bf16.h>
#include <cstdint>

#define FULL 0xffffffffu

// Order-preserving float->uint map: a > b  <=>  f2o(a) > f2o(b)
__device__ __forceinline__ unsigned f2o(float f) {
    unsigned b = __float_as_uint(f);
    return b ^ ((unsigned)((int)b >> 31) | 0x80000000u);
}

// One warp per token. E = 256 experts, 8 groups of 32.
// Lane l owns experts [l*8, l*8+8) -> all in group (l>>2); groups = 4-lane segments.
__global__ void __launch_bounds__(256)
noaux_router_kernel(const float* __restrict__ logits,
                    const float* __restrict__ bias,
                    float* __restrict__ out,
                    int T, int write_ids)
{
    const int warp = blockIdx.x * (blockDim.x >> 5) + (threadIdx.x >> 5);
    if (warp >= T) return;
    const int lane = threadIdx.x & 31;

    // ---- load 8 logits + 8 biases (2x LDG.128 each) ----
    const float4* lp = reinterpret_cast<const float4*>(logits + (size_t)warp * 256);
    float4 x0 = lp[lane * 2];
    float4 x1 = lp[lane * 2 + 1];
    const float4* bp = reinterpret_cast<const float4*>(bias);
    float4 b0 = bp[lane * 2];
    float4 b1 = bp[lane * 2 + 1];

    float xv[8] = {x0.x, x0.y, x0.z, x0.w, x1.x, x1.y, x1.z, x1.w};
    float bv[8] = {b0.x, b0.y, b0.z, b0.w, b1.x, b1.y, b1.z, b1.w};

    // corrected score (selection only); uncorrected sigmoid recomputed at the end
    float mk[8];
    #pragma unroll
    for (int i = 0; i < 8; i++) {
        float e = __expf(-xv[i]);
        mk[i] = 1.0f / (1.0f + e) + bv[i];
    }

    // ---- group score = sum of top-2 corrected within group ----
    float m1 = -INFINITY, m2 = -INFINITY;
    #pragma unroll
    for (int i = 0; i < 8; i++) {
        float v   = mk[i];
        float nm2 = fmaxf(m2, fminf(m1, v));
        m1 = fmaxf(m1, v);
        m2 = nm2;
    }
    #pragma unroll
    for (int d = 1; d < 4; d <<= 1) {    // reduce within 4-lane group segment
        float o1 = __shfl_xor_sync(FULL, m1, d);
        float o2 = __shfl_xor_sync(FULL, m2, d);
        float nm2 = fmaxf(fminf(m1, o1), fmaxf(m2, o2));
        m1 = fmaxf(m1, o1);
        m2 = nm2;
    }
    const float gscore = m1 + m2;        // identical across each 4-lane segment
    const int   myg    = lane >> 2;

    // ---- top-4 groups (tie-break: lowest group index) ----
    float gs[8];
    #pragma unroll
    for (int g = 0; g < 8; g++) gs[g] = __shfl_sync(FULL, gscore, g * 4);
    int cnt = 0;
    const float s_my = gs[myg];
    #pragma unroll
    for (int g = 0; g < 8; g++)
        cnt += (gs[g] > s_my) || (gs[g] == s_my && g < myg);
    const bool sel = (cnt < 4);

    // ---- mask + convert to integer keys (0 = removed sentinel, < all real keys) ----
    unsigned ik[8];
    #pragma unroll
    for (int i = 0; i < 8; i++)
        ik[i] = f2o(sel ? mk[i] : 0.0f);

    // ---- local argmax (keep FIRST slot on ties -> lowest index) ----
    unsigned mkey = ik[0]; int midx = 0;
    #pragma unroll
    for (int i = 1; i < 8; i++)
        if (ik[i] > mkey) { mkey = ik[i]; midx = i; }

    // ---- global top-8: 8 rounds of REDUX argmax ----
    int myid = 0;
    #pragma unroll
    for (int it = 0; it < 8; it++) {
        unsigned m    = __reduce_max_sync(FULL, mkey);
        unsigned ball = __ballot_sync(FULL, mkey == m);
        int wlane     = __ffs(ball) - 1;              // lowest lane = lowest expert idx
        int smidx     = __shfl_sync(FULL, midx, wlane);
        int gi        = (wlane << 3) | smidx;
        if (lane == it) myid = gi;

        // remove winner slot (predicated, no dynamic indexing)
        const bool win = (lane == wlane);
        #pragma unroll
        for (int i = 0; i < 8; i++)
            if (win && i == midx) ik[i] = 0u;

        // rescan (only winner's state actually changes)
        mkey = ik[0]; midx = 0;
        #pragma unroll
        for (int i = 1; i < 8; i++)
            if (ik[i] > mkey) { mkey = ik[i]; midx = i; }
    }

    // ---- epilogue: lanes 0-7 recompute uncorrected sigmoid of their winner ----
    float w = 0.0f;
    if (lane < 8) {
        float x = __ldg(logits + (size_t)warp * 256 + myid);
        w = 1.0f / (1.0f + __expf(-x));
    }
    // sum across lanes 0-7 (xor pattern stays within the 8-lane group)
    float wsum = w;
    #pragma unroll
    for (int d = 1; d < 8; d <<= 1)
        wsum += __shfl_xor_sync(FULL, wsum, d);

    if (lane < 8) {
        const float scale = 2.5f / (wsum + 1e-20f);
        out[(size_t)warp * 8 + lane] = w * scale;
        if (write_ids)
            out[(size_t)T * 8 + (size_t)warp * 8 + lane] = (float)myid;
    }
}

extern "C" void kernel_launch(void* const* d_in, const int* in_sizes, int n_in,
                              void* d_out, int out_size)
{
    const float* logits = (const float*)d_in[0];
    const float* bias   = (const float*)d_in[1];
    const int E = in_sizes[1];            // 256
    const int T = in_sizes[0] / E;        // 131072
    float* out = (float*)d_out;

    const int write_ids = (out_size >= T * 16) ? 1 : 0;

    const int warps_per_block = 8;        // 256 threads
    const int blocks = (T + warps_per_block - 1) / warps_per_block;
    noaux_router_kernel<<<blocks, 256>>>(logits, bias, out, T, write_ids);
}

// round 3
// speedup vs baseline: 2.5874x; 1.5290x over previous
#include <cuda_runtime.h>
#include <cuda_bf16.h>
#include <cstdint>

#define FULL 0xffffffffu

// Order-preserving float->uint map: a > b  <=>  f2o(a) > f2o(b)
__device__ __forceinline__ unsigned f2o(float f) {
    unsigned b = __float_as_uint(f);
    return b ^ ((unsigned)((int)b >> 31) | 0x80000000u);
}

// stable descending compare-exchange on (key,id) pairs: larger key first;
// equal keys keep original order (lower id first, ids start ascending in-lane)
#define CSWAP(ka, kb, ia, ib)                          \
    {                                                  \
        bool p = (ka) < (kb);                          \
        unsigned tk = p ? (kb) : (ka);                 \
        (kb) = p ? (ka) : (kb);                        \
        (ka) = tk;                                     \
        int ti = p ? (ib) : (ia);                      \
        (ib) = p ? (ia) : (ib);                        \
        (ia) = ti;                                     \
    }

// One warp per token. E = 256 experts, 8 groups of 32.
// Lane l owns experts [l*8, l*8+8) -> group (l>>2); groups are 4-lane segments.
__global__ void __launch_bounds__(256)
noaux_router_kernel(const float* __restrict__ logits,
                    const float* __restrict__ bias,
                    float* __restrict__ out,
                    int T, int write_ids)
{
    const int warp = blockIdx.x * (blockDim.x >> 5) + (threadIdx.x >> 5);
    if (warp >= T) return;
    const int lane = threadIdx.x & 31;

    // ---- load 8 logits + 8 biases (2x LDG.128 each) ----
    const float4* lp = reinterpret_cast<const float4*>(logits + (size_t)warp * 256);
    float4 x0 = lp[lane * 2];
    float4 x1 = lp[lane * 2 + 1];
    const float4* bp = reinterpret_cast<const float4*>(bias);
    float4 b0 = bp[lane * 2];
    float4 b1 = bp[lane * 2 + 1];

    float xv[8] = {x0.x, x0.y, x0.z, x0.w, x1.x, x1.y, x1.z, x1.w};
    float bv[8] = {b0.x, b0.y, b0.z, b0.w, b1.x, b1.y, b1.z, b1.w};

    // corrected score (selection only)
    float mk[8];
    #pragma unroll
    for (int i = 0; i < 8; i++) {
        float e = __expf(-xv[i]);
        mk[i] = 1.0f / (1.0f + e) + bv[i];
    }

    // ---- group score = sum of top-2 corrected within group ----
    float m1 = -INFINITY, m2 = -INFINITY;
    #pragma unroll
    for (int i = 0; i < 8; i++) {
        float v   = mk[i];
        float nm2 = fmaxf(m2, fminf(m1, v));
        m1 = fmaxf(m1, v);
        m2 = nm2;
    }
    #pragma unroll
    for (int d = 1; d < 4; d <<= 1) {    // reduce within 4-lane group segment
        float o1 = __shfl_xor_sync(FULL, m1, d);
        float o2 = __shfl_xor_sync(FULL, m2, d);
        float nm2 = fmaxf(fminf(m1, o1), fmaxf(m2, o2));
        m1 = fmaxf(m1, o1);
        m2 = nm2;
    }
    const float gscore = m1 + m2;        // uniform across each 4-lane segment
    const int   myg    = lane >> 2;

    // ---- top-4 groups (tie-break: lowest group index) ----
    float gs[8];
    #pragma unroll
    for (int g = 0; g < 8; g++) gs[g] = __shfl_sync(FULL, gscore, g * 4);
    int cnt = 0;
    const float s_my = gs[myg];
    #pragma unroll
    for (int g = 0; g < 8; g++)
        cnt += (gs[g] > s_my) || (gs[g] == s_my && g < myg);
    const bool sel = (cnt < 4);

    // ---- redistribute: 128 live candidates -> 4 per lane ----
    // gb: one bit per group at position 4g (selected); dgb: dead groups
    const unsigned sball = __ballot_sync(FULL, sel);
    const unsigned gb  = sball & 0x11111111u;
    const unsigned dgb = ~sball & 0x11111111u;
    const int g4 = lane & ~3;            // 4 * my group
    const int s  = lane & 3;

    int src = lane;                      // live lanes source from themselves
    if (!sel) {
        // rank among dead groups
        int need = __popc(dgb & ((1u << g4) - 1u)) + 1;
        // (need)-th set nibble-bit of gb -> partner selected group
        int p4 = 0;
        int c = __popc(gb & 0xFFFFu);
        unsigned seg = gb;
        if (need > c) { need -= c; p4 = 16; seg >>= 16; }
        c = __popc(seg & 0xFFu);
        if (need > c) { need -= c; p4 += 8; seg >>= 8; }
        c = __popc(seg & 0xFu);
        if (need > c) { p4 += 4; }
        src = p4 + s;                    // partner live lane
    }

    // every lane provides keys of its slots 4..7; dead lanes pull from partner
    unsigned k0, k1, k2, k3;
    int i0, i1, i2, i3;
    {
        unsigned u0 = __shfl_sync(FULL, f2o(mk[4]), src);
        unsigned u1 = __shfl_sync(FULL, f2o(mk[5]), src);
        unsigned u2 = __shfl_sync(FULL, f2o(mk[6]), src);
        unsigned u3 = __shfl_sync(FULL, f2o(mk[7]), src);
        k0 = sel ? f2o(mk[0]) : u0;
        k1 = sel ? f2o(mk[1]) : u1;
        k2 = sel ? f2o(mk[2]) : u2;
        k3 = sel ? f2o(mk[3]) : u3;
        const int base = sel ? (lane << 3) : ((src << 3) + 4);
        i0 = base;  i1 = base + 1;  i2 = base + 2;  i3 = base + 3;
    }

    // ---- sort 4 descending (stable) ----
    CSWAP(k0, k1, i0, i1);
    CSWAP(k2, k3, i2, i3);
    CSWAP(k0, k2, i0, i2);
    CSWAP(k1, k3, i1, i3);
    CSWAP(k1, k2, i1, i2);

    // ---- global top-8: 8 rounds of REDUX over sorted heads ----
    int myid = 0;
    #pragma unroll
    for (int it = 0; it < 8; it++) {
        unsigned m    = __reduce_max_sync(FULL, k0);
        unsigned ball = __ballot_sync(FULL, k0 == m);
        int wl        = __ffs(ball) - 1;
        int wid       = __shfl_sync(FULL, i0, wl);
        if (lane == it) myid = wid;
        const bool win = (lane == wl);
        k0 = win ? k1 : k0;  i0 = win ? i1 : i0;
        k1 = win ? k2 : k1;  i1 = win ? i2 : i1;
        k2 = win ? k3 : k2;  i2 = win ? i3 : i2;
        k3 = win ? 0u : k3;
    }

    // ---- epilogue: lanes 0-7 recompute uncorrected sigmoid of their winner ----
    float w = 0.0f;
    if (lane < 8) {
        float x = __ldg(logits + (size_t)warp * 256 + myid);
        w = 1.0f / (1.0f + __expf(-x));
    }
    float wsum = w;
    #pragma unroll
    for (int d = 1; d < 8; d <<= 1)
        wsum += __shfl_xor_sync(FULL, wsum, d);

    if (lane < 8) {
        const float scale = 2.5f / (wsum + 1e-20f);
        out[(size_t)warp * 8 + lane] = w * scale;
        if (write_ids)
            out[(size_t)T * 8 + (size_t)warp * 8 + lane] = (float)myid;
    }
}

extern "C" void kernel_launch(void* const* d_in, const int* in_sizes, int n_in,
                              void* d_out, int out_size)
{
    const float* logits = (const float*)d_in[0];
    const float* bias   = (const float*)d_in[1];
    const int E = in_sizes[1];            // 256
    const int T = in_sizes[0] / E;        // 131072
    float* out = (float*)d_out;

    const int write_ids = (out_size >= T * 16) ? 1 : 0;

    const int warps_per_block = 8;        // 256 threads
    const int blocks = (T + warps_per_block - 1) / warps_per_block;
    noaux_router_kernel<<<blocks, 256>>>(logits, bias, out, T, write_ids);
}